// round 3
// baseline (speedup 1.0000x reference)
#include <cuda_runtime.h>
#include <cuda_bf16.h>

#define EPS 1e-16f
#define W 1024
#define H 1024
#define ROWS 4          // output rows per thread/block
#define TPB 256         // 256 threads * 4 px = 1024 = full row width

__global__ __launch_bounds__(TPB)
void curvature_kernel(const float* __restrict__ u, float* __restrict__ out) {
    // block handles ROWS rows x full width of one batch image
    const int tile = blockIdx.x;            // b * (H/ROWS) + row-tile
    const int b    = tile >> 8;             // H/ROWS = 256 tiles per image
    const int x0   = (tile & 255) * ROWS;   // first output row
    const int y    = threadIdx.x * 4;       // first output col (float4 granule)

    const float* ub = u   + (size_t)b * (H * W);
    float*       ob = out + (size_t)b * (H * W);

    // ---- 6 row-vectors (rows x0-1 .. x0+4) at col y, reflect-clamped in x ----
    float rows[ROWS + 2][4];
    #pragma unroll
    for (int i = 0; i < ROWS + 2; ++i) {
        int r = x0 - 1 + i;
        r = (r < 0) ? 1 : ((r >= H) ? (H - 2) : r);
        float4 v = *reinterpret_cast<const float4*>(ub + (size_t)r * W + y);
        rows[i][0] = v.x; rows[i][1] = v.y; rows[i][2] = v.z; rows[i][3] = v.w;
    }

    // reflect-clamped side columns
    const int yl = (y == 0)       ? 1       : (y - 1);
    const int yr = (y + 4 >= W)   ? (W - 2) : (y + 4);

    // left[i]  = u[reflect(x0+i)  , yl]   for i = 0..ROWS   (rows x0 .. x0+4)
    // right[i] = u[reflect(x0-1+i), yr]   for i = 0..ROWS   (rows x0-1 .. x0+3)
    float lft_col[ROWS + 1], rgt_col[ROWS + 1];
    #pragma unroll
    for (int i = 0; i <= ROWS; ++i) {
        int rL = x0 + i;            // never < 0
        rL = (rL >= H) ? (H - 2) : rL;
        lft_col[i] = __ldg(ub + (size_t)rL * W + yl);
        int rR = x0 - 1 + i;        // never >= H
        rR = (rR < 0) ? 1 : rR;
        rgt_col[i] = __ldg(ub + (size_t)rR * W + yr);
    }

    // ---- compute ROWS x 4 outputs ----
    #pragma unroll
    for (int i = 0; i < ROWS; ++i) {
        float res[4];
        #pragma unroll
        for (int j = 0; j < 4; ++j) {
            const float c    = rows[i + 1][j];                          // u[x, y+j]
            const float up   = rows[i][j];                              // u[x-1, y+j]
            const float dn   = rows[i + 2][j];                          // u[x+1, y+j]
            const float rgt  = (j < 3) ? rows[i + 1][j + 1] : rgt_col[i + 1]; // u[x, y+j+1]
            const float lft  = (j > 0) ? rows[i + 1][j - 1] : lft_col[i];     // u[x, y+j-1]
            const float up_r = (j < 3) ? rows[i][j + 1]     : rgt_col[i];     // u[x-1, y+j+1]
            const float dn_l = (j > 0) ? rows[i + 2][j - 1] : lft_col[i + 1]; // u[x+1, y+j-1]

            const float dxf  = dn   - c;
            const float dxb  = c    - up;
            const float dyf  = rgt  - c;
            const float dyb  = c    - lft;
            const float dsbf = up_r - up;    // u[x-1,y+1] - u[x-1,y]
            const float dslf = dn_l - lft;   // u[x+1,y-1] - u[x,  y-1]

            const float invF = rsqrtf(fmaf(dxf, dxf, fmaf(dyf, dyf, EPS)));
            const float invG = rsqrtf(fmaf(dxb, dxb, fmaf(dsbf, dsbf, EPS)));
            const float invH = rsqrtf(fmaf(dslf, dslf, fmaf(dyb, dyb, EPS)));

            res[j] = (dxf + dyf) * invF - dxb * invG - dyb * invH;
        }
        float4 o;
        o.x = res[0]; o.y = res[1]; o.z = res[2]; o.w = res[3];
        *reinterpret_cast<float4*>(ob + (size_t)(x0 + i) * W + y) = o;
    }
}

extern "C" void kernel_launch(void* const* d_in, const int* in_sizes, int n_in,
                              void* d_out, int out_size) {
    const float* u = (const float*)d_in[0];
    float* out = (float*)d_out;
    const int batch = in_sizes[0] / (H * W);   // 16
    const int blocks = batch * (H / ROWS);     // 4096
    curvature_kernel<<<blocks, TPB>>>(u, out);
}